// round 10
// baseline (speedup 1.0000x reference)
#include <cuda_runtime.h>
#include <math.h>

#define BATCH   4096
#define VOCAB   32000
#define NVEC    (VOCAB / 4)      /* 8000 float4 per row */
#define THREADS 512
#define NWARP   (THREADS / 32)

// Per-row partial: (A/BATCH)*ce_i + B_COEF*neg_i. Fully rewritten by every
// launch (one block per row) -> no init needed, deterministic.
__device__ float g_row[BATCH];

__device__ __forceinline__ float warp_red_sum(float v) {
#pragma unroll
    for (int o = 16; o > 0; o >>= 1) v += __shfl_xor_sync(0xffffffffu, v, o);
    return v;
}
__device__ __forceinline__ float warp_red_max(float v) {
#pragma unroll
    for (int o = 16; o > 0; o >>= 1) v = fmaxf(v, __shfl_xor_sync(0xffffffffu, v, o));
    return v;
}

__device__ __forceinline__ void accum4(const float4 v, float& m, float& sexp,
                                       float& s, float& ss)
{
    s += (v.x + v.y) + (v.z + v.w);
    ss = fmaf(v.x, v.x, ss);
    ss = fmaf(v.y, v.y, ss);
    ss = fmaf(v.z, v.z, ss);
    ss = fmaf(v.w, v.w, ss);

    float m4 = fmaxf(fmaxf(v.x, v.y), fmaxf(v.z, v.w));
    if (m4 > m) {                    // rarely taken after warm-up
        sexp *= __expf(m - m4);      // first hit: exp(-inf)=0, sexp stays 0
        m = m4;
    }
    sexp += __expf(v.x - m);
    sexp += __expf(v.y - m);
    sexp += __expf(v.z - m);
    sexp += __expf(v.w - m);
}

__global__ __launch_bounds__(THREADS)
void row_kernel(const float* __restrict__ pred, const int* __restrict__ labels)
{
    const int row  = blockIdx.x;
    const int tid  = threadIdx.x;
    const int lane = tid & 31;
    const int wid  = tid >> 5;

    const float4* __restrict__ p =
        reinterpret_cast<const float4*>(pred + (size_t)row * VOCAB);

    float m = -3.402823466e38f;
    float sexp = 0.0f, s = 0.0f, ss = 0.0f;

    // Unroll x2: issue both 16B loads back-to-back (MLP), then do the math.
    int i = tid;
    for (; i + THREADS < NVEC; i += 2 * THREADS) {
        float4 a = __ldg(p + i);
        float4 b = __ldg(p + i + THREADS);
        accum4(a, m, sexp, s, ss);
        accum4(b, m, sexp, s, ss);
    }
    if (i < NVEC) {                  // tail for tid >= 320 (8000 = 15*512 + 320)
        float4 a = __ldg(p + i);
        accum4(a, m, sexp, s, ss);
    }

    __shared__ float shm[NWARP];
    __shared__ float she[NWARP];
    __shared__ float shs[NWARP];
    __shared__ float shq[NWARP];
    __shared__ float shM;

    // Block max
    float wm = warp_red_max(m);
    if (lane == 0) shm[wid] = wm;
    __syncthreads();
    if (tid == 0) {
        float M = shm[0];
#pragma unroll
        for (int k = 1; k < NWARP; k++) M = fmaxf(M, shm[k]);
        shM = M;
    }
    __syncthreads();
    const float M = shM;

    // Renormalize exp-sum to block max; block-sum all three accumulators.
    float e   = sexp * __expf(m - M);
    float we  = warp_red_sum(e);
    float wsv = warp_red_sum(s);
    float wq  = warp_red_sum(ss);
    if (lane == 0) { she[wid] = we; shs[wid] = wsv; shq[wid] = wq; }
    __syncthreads();

    if (tid == 0) {
        float Se = 0.0f, Ss = 0.0f, Sq = 0.0f;
#pragma unroll
        for (int k = 0; k < NWARP; k++) { Se += she[k]; Ss += shs[k]; Sq += shq[k]; }

        int lab = labels[row];       // int32: JAX default (x64 disabled)
        float tgt = __ldg(pred + (size_t)row * VOCAB + (size_t)lab);

        // CE for this row: logsumexp - target logit
        float logS = M + logf(Se);
        float ce_i = logS - tgt;

        // Exclude-target sum / sumsq -> sum of squared deviations from mean
        float snt   = Ss - tgt;
        float ssnt  = Sq - tgt * tgt;
        float neg_i = ssnt - (snt * snt) * (1.0f / (float)(VOCAB - 1));

        // A = 1.0 (mean CE -> 1/BATCH), B_COEF = 0.005 (sum over rows)
        g_row[row] = ce_i * (1.0f / (float)BATCH) + 0.005f * neg_i;
    }
}

__global__ __launch_bounds__(1024)
void final_reduce(float* __restrict__ out)
{
    const int tid = threadIdx.x;
    double acc = 0.0;
    for (int k = tid; k < BATCH; k += 1024) acc += (double)g_row[k];

    __shared__ double db[1024];
    db[tid] = acc;
    __syncthreads();
    for (int o = 512; o > 0; o >>= 1) {
        if (tid < o) db[tid] += db[tid + o];
        __syncthreads();
    }
    if (tid == 0) out[0] = (float)db[0];
}

extern "C" void kernel_launch(void* const* d_in, const int* in_sizes, int n_in,
                              void* d_out, int out_size)
{
    const float* pred   = (const float*)d_in[0];
    const int*   labels = (const int*)d_in[1];
    (void)in_sizes; (void)n_in; (void)out_size;

    row_kernel<<<BATCH, THREADS>>>(pred, labels);
    final_reduce<<<1, 1024>>>((float*)d_out);
}

// round 11
// speedup vs baseline: 1.0385x; 1.0385x over previous
#include <cuda_runtime.h>
#include <math.h>

#define BATCH   4096
#define VOCAB   32000
#define NVEC    (VOCAB / 4)      /* 8000 float4 per row */
#define THREADS 512
#define NWARP   (THREADS / 32)

// Per-row partial: (A/BATCH)*ce_i + B_COEF*neg_i. Fully rewritten by every
// launch (one block per row) -> no init needed, deterministic.
__device__ float g_row[BATCH];

__device__ __forceinline__ float warp_red_sum(float v) {
#pragma unroll
    for (int o = 16; o > 0; o >>= 1) v += __shfl_xor_sync(0xffffffffu, v, o);
    return v;
}
__device__ __forceinline__ float warp_red_max(float v) {
#pragma unroll
    for (int o = 16; o > 0; o >>= 1) v = fmaxf(v, __shfl_xor_sync(0xffffffffu, v, o));
    return v;
}
__device__ __forceinline__ double warp_red_sum_d(double v) {
#pragma unroll
    for (int o = 16; o > 0; o >>= 1) v += __shfl_xor_sync(0xffffffffu, v, o);
    return v;
}

__device__ __forceinline__ void accum4(const float4 v, float& m, float& sexp,
                                       float& s, float& ss)
{
    s += (v.x + v.y) + (v.z + v.w);
    ss = fmaf(v.x, v.x, ss);
    ss = fmaf(v.y, v.y, ss);
    ss = fmaf(v.z, v.z, ss);
    ss = fmaf(v.w, v.w, ss);

    float m4 = fmaxf(fmaxf(v.x, v.y), fmaxf(v.z, v.w));
    if (m4 > m) {                    // rarely taken after warm-up
        sexp *= __expf(m - m4);      // first hit: exp(-inf)=0, sexp stays 0
        m = m4;
    }
    sexp += __expf(v.x - m);
    sexp += __expf(v.y - m);
    sexp += __expf(v.z - m);
    sexp += __expf(v.w - m);
}

__global__ __launch_bounds__(THREADS)
void row_kernel(const float* __restrict__ pred, const int* __restrict__ labels)
{
    const int row  = blockIdx.x;
    const int tid  = threadIdx.x;
    const int lane = tid & 31;
    const int wid  = tid >> 5;

    const float4* __restrict__ p =
        reinterpret_cast<const float4*>(pred + (size_t)row * VOCAB);

    float m = -3.402823466e38f;
    float sexp = 0.0f, s = 0.0f, ss = 0.0f;

    // Unroll x4: issue all four 16B loads back-to-back (MLP=4/thread), then math.
    int i = tid;
    for (; i + 3 * THREADS < NVEC; i += 4 * THREADS) {
        float4 a = __ldg(p + i);
        float4 b = __ldg(p + i +     THREADS);
        float4 c = __ldg(p + i + 2 * THREADS);
        float4 d = __ldg(p + i + 3 * THREADS);
        accum4(a, m, sexp, s, ss);
        accum4(b, m, sexp, s, ss);
        accum4(c, m, sexp, s, ss);
        accum4(d, m, sexp, s, ss);
    }
    for (; i < NVEC; i += THREADS) {
        float4 a = __ldg(p + i);
        accum4(a, m, sexp, s, ss);
    }

    __shared__ float shm[NWARP];
    __shared__ float she[NWARP];
    __shared__ float shs[NWARP];
    __shared__ float shq[NWARP];
    __shared__ float shM;

    // Block max
    float wm = warp_red_max(m);
    if (lane == 0) shm[wid] = wm;
    __syncthreads();
    if (tid == 0) {
        float M = shm[0];
#pragma unroll
        for (int k = 1; k < NWARP; k++) M = fmaxf(M, shm[k]);
        shM = M;
    }
    __syncthreads();
    const float M = shM;

    // Renormalize exp-sum to block max; block-sum all three accumulators.
    float e   = sexp * __expf(m - M);
    float we  = warp_red_sum(e);
    float wsv = warp_red_sum(s);
    float wq  = warp_red_sum(ss);
    if (lane == 0) { she[wid] = we; shs[wid] = wsv; shq[wid] = wq; }
    __syncthreads();

    if (tid == 0) {
        float Se = 0.0f, Ss = 0.0f, Sq = 0.0f;
#pragma unroll
        for (int k = 0; k < NWARP; k++) { Se += she[k]; Ss += shs[k]; Sq += shq[k]; }

        int lab = labels[row];       // int32 (JAX default: x64 disabled)
        float tgt = __ldg(pred + (size_t)row * VOCAB + (size_t)lab);

        // CE for this row: logsumexp - target logit
        float logS = M + logf(Se);
        float ce_i = logS - tgt;

        // Exclude-target sum / sumsq -> sum of squared deviations from mean
        float snt   = Ss - tgt;
        float ssnt  = Sq - tgt * tgt;
        float neg_i = ssnt - (snt * snt) * (1.0f / (float)(VOCAB - 1));

        // A = 1.0 (mean CE -> 1/BATCH), B_COEF = 0.005 (sum over rows)
        g_row[row] = ce_i * (1.0f / (float)BATCH) + 0.005f * neg_i;
    }
}

// 128 threads, float4 loads, double accumulation, warp-shuffle tree,
// a single barrier. 4096 floats = 1024 float4 = 128 threads x 8 vectors.
__global__ __launch_bounds__(128)
void final_reduce(float* __restrict__ out)
{
    const int tid  = threadIdx.x;
    const int lane = tid & 31;
    const int wid  = tid >> 5;

    const float4* g4 = reinterpret_cast<const float4*>(g_row);

    double acc = 0.0;
#pragma unroll
    for (int k = 0; k < 8; k++) {
        float4 v = g4[tid + k * 128];
        acc += ((double)v.x + (double)v.y) + ((double)v.z + (double)v.w);
    }

    acc = warp_red_sum_d(acc);

    __shared__ double sh[4];
    if (lane == 0) sh[wid] = acc;
    __syncthreads();
    if (tid == 0)
        out[0] = (float)(((sh[0] + sh[1]) + (sh[2] + sh[3])));
}

extern "C" void kernel_launch(void* const* d_in, const int* in_sizes, int n_in,
                              void* d_out, int out_size)
{
    const float* pred   = (const float*)d_in[0];
    const int*   labels = (const int*)d_in[1];
    (void)in_sizes; (void)n_in; (void)out_size;

    row_kernel<<<BATCH, THREADS>>>(pred, labels);
    final_reduce<<<1, 128>>>((float*)d_out);
}